// round 1
// baseline (speedup 1.0000x reference)
#include <cuda_runtime.h>
#include <math.h>

#define H   768
#define F   3072
#define E   8
#define NTOK 1024
#define CAP 1024            // per-expert row capacity (worst case: all tokens pick same expert)
#define ROWS (E*CAP)        // 8192 gathered rows (only 2048 active)

// ---- scratch (static device globals; no runtime allocation) ----
__device__ int   g_cnt[E];
__device__ int   g_tok[ROWS];        // token index per gathered row
__device__ float g_rw[ROWS];         // gate weight per gathered row
__device__ int   g_slot_row[NTOK*2]; // per-token: its two gathered rows
__device__ float g_h[ROWS * F];      // gelu(x @ w1)  (100 MB static, ~25 MB touched)
__device__ float g_y[ROWS * H];      // h @ w2 * gate

// ---------------------------------------------------------------
__global__ void zero_cnt_kernel() {
    if (threadIdx.x < E) g_cnt[threadIdx.x] = 0;
}

// One warp per token: logits = x[n] @ router_w, top-2, renormalized gates.
__global__ void router_kernel(const float* __restrict__ x,
                              const float* __restrict__ rw) {
    int warp = (blockIdx.x * blockDim.x + threadIdx.x) >> 5;
    int lane = threadIdx.x & 31;
    if (warp >= NTOK) return;
    const float* xr = x + warp * H;

    float acc[E];
#pragma unroll
    for (int e = 0; e < E; e++) acc[e] = 0.f;

    for (int k = lane; k < H; k += 32) {
        float xv = xr[k];
        const float* r = rw + k * E;
#pragma unroll
        for (int e = 0; e < E; e++) acc[e] += xv * r[e];
    }
#pragma unroll
    for (int e = 0; e < E; e++) {
#pragma unroll
        for (int o = 16; o > 0; o >>= 1)
            acc[e] += __shfl_down_sync(0xffffffffu, acc[e], o);
    }
    if (lane == 0) {
        float b0 = -INFINITY, b1 = -INFINITY;
        int i0 = 0, i1 = 0;
#pragma unroll
        for (int e = 0; e < E; e++) {
            float v = acc[e];
            if (v > b0) { b1 = b0; i1 = i0; b0 = v; i0 = e; }
            else if (v > b1) { b1 = v; i1 = e; }
        }
        // renormalized top-2 softmax weights (exactly softmax over {b0,b1})
        float s  = expf(b1 - b0);
        float w0 = 1.f / (1.f + s);
        float w1 = s / (1.f + s);

        int p0 = atomicAdd(&g_cnt[i0], 1);
        int r0 = i0 * CAP + p0;
        g_tok[r0] = warp; g_rw[r0] = w0; g_slot_row[warp * 2 + 0] = r0;

        int p1 = atomicAdd(&g_cnt[i1], 1);
        int r1 = i1 * CAP + p1;
        g_tok[r1] = warp; g_rw[r1] = w1; g_slot_row[warp * 2 + 1] = r1;
    }
}

__device__ __forceinline__ float gelu_exact(float v) {
    return 0.5f * v * (1.0f + erff(v * 0.70710678118654752f));
}

// ---------------------------------------------------------------
// GEMM1: h[row, f] = gelu( x[tok[row], :] @ w1[e, :, f] )
// 128x128 tile, BK=8, 256 threads, 8x8 per thread.
__global__ void __launch_bounds__(256, 2)
gemm1_kernel(const float* __restrict__ x, const float* __restrict__ w1) {
    const int e   = blockIdx.z;
    const int cnt = g_cnt[e];
    const int m0  = blockIdx.y * 128;
    if (m0 >= cnt) return;
    const int n0  = blockIdx.x * 128;

    __shared__ float As[8][128];
    __shared__ float Bs[8][128];

    const int t  = threadIdx.x;
    const int tx = t & 15, ty = t >> 4;

    // A (gathered) load mapping: thread -> (row, 4-float seg of K)
    const int arow = t >> 1;
    const int aseg = (t & 1) * 4;
    const bool avalid = (m0 + arow) < cnt;
    const int  grow_a = e * CAP + m0 + arow;
    const float* aptr = x + (size_t)(avalid ? g_tok[grow_a] : 0) * H;

    // B load mapping: thread -> (k row 0..7, 4-float seg of N)
    const int brow = t >> 5;
    const int bcol = (t & 31) * 4;
    const float* bptr = w1 + (size_t)e * H * F + (size_t)brow * F + n0 + bcol;

    float acc[8][8];
#pragma unroll
    for (int i = 0; i < 8; i++)
#pragma unroll
        for (int j = 0; j < 8; j++) acc[i][j] = 0.f;

    for (int k0 = 0; k0 < H; k0 += 8) {
        float4 av = *(const float4*)(aptr + k0 + aseg);
        if (!avalid) av = make_float4(0.f, 0.f, 0.f, 0.f);
        float4 bv = *(const float4*)(bptr + (size_t)k0 * F);

        As[aseg + 0][arow] = av.x;
        As[aseg + 1][arow] = av.y;
        As[aseg + 2][arow] = av.z;
        As[aseg + 3][arow] = av.w;
        *(float4*)&Bs[brow][bcol] = bv;
        __syncthreads();

#pragma unroll
        for (int k = 0; k < 8; k++) {
            float a[8], b[8];
#pragma unroll
            for (int i = 0; i < 8; i++) a[i] = As[k][ty * 8 + i];
#pragma unroll
            for (int j = 0; j < 8; j++) b[j] = Bs[k][tx * 8 + j];
#pragma unroll
            for (int i = 0; i < 8; i++)
#pragma unroll
                for (int j = 0; j < 8; j++) acc[i][j] += a[i] * b[j];
        }
        __syncthreads();
    }

#pragma unroll
    for (int i = 0; i < 8; i++) {
        int m = m0 + ty * 8 + i;
        if (m >= cnt) continue;
        float* hrow = g_h + (size_t)(e * CAP + m) * F + n0 + tx * 8;
#pragma unroll
        for (int j = 0; j < 8; j++) hrow[j] = gelu_exact(acc[i][j]);
    }
}

// ---------------------------------------------------------------
// GEMM2: y[row, h] = gate[row] * ( h[row, :] @ w2[e, :, h] )
__global__ void __launch_bounds__(256, 2)
gemm2_kernel(const float* __restrict__ w2) {
    const int e   = blockIdx.z;
    const int cnt = g_cnt[e];
    const int m0  = blockIdx.y * 128;
    if (m0 >= cnt) return;
    const int n0  = blockIdx.x * 128;

    __shared__ float As[8][128];
    __shared__ float Bs[8][128];

    const int t  = threadIdx.x;
    const int tx = t & 15, ty = t >> 4;

    const int arow = t >> 1;
    const int aseg = (t & 1) * 4;
    const bool avalid = (m0 + arow) < cnt;
    const int  grow_a = e * CAP + m0 + arow;
    const float* aptr = g_h + (size_t)(avalid ? grow_a : e * CAP) * F;

    const int brow = t >> 5;
    const int bcol = (t & 31) * 4;
    const float* bptr = w2 + (size_t)e * F * H + (size_t)brow * H + n0 + bcol;

    float acc[8][8];
#pragma unroll
    for (int i = 0; i < 8; i++)
#pragma unroll
        for (int j = 0; j < 8; j++) acc[i][j] = 0.f;

    for (int k0 = 0; k0 < F; k0 += 8) {
        float4 av = *(const float4*)(aptr + k0 + aseg);
        if (!avalid) av = make_float4(0.f, 0.f, 0.f, 0.f);
        float4 bv = *(const float4*)(bptr + (size_t)k0 * H);

        As[aseg + 0][arow] = av.x;
        As[aseg + 1][arow] = av.y;
        As[aseg + 2][arow] = av.z;
        As[aseg + 3][arow] = av.w;
        *(float4*)&Bs[brow][bcol] = bv;
        __syncthreads();

#pragma unroll
        for (int k = 0; k < 8; k++) {
            float a[8], b[8];
#pragma unroll
            for (int i = 0; i < 8; i++) a[i] = As[k][ty * 8 + i];
#pragma unroll
            for (int j = 0; j < 8; j++) b[j] = Bs[k][tx * 8 + j];
#pragma unroll
            for (int i = 0; i < 8; i++)
#pragma unroll
                for (int j = 0; j < 8; j++) acc[i][j] += a[i] * b[j];
        }
        __syncthreads();
    }

#pragma unroll
    for (int i = 0; i < 8; i++) {
        int m = m0 + ty * 8 + i;
        if (m >= cnt) continue;
        int grow = e * CAP + m;
        float gate = g_rw[grow];
        float* yrow = g_y + (size_t)grow * H + n0 + tx * 8;
#pragma unroll
        for (int j = 0; j < 8; j++) yrow[j] = gate * acc[i][j];
    }
}

// ---------------------------------------------------------------
// out[n, h] = y[slot0(n), h] + y[slot1(n), h]   (float4 vectorized)
__global__ void combine_kernel(float* __restrict__ out) {
    int idx = blockIdx.x * blockDim.x + threadIdx.x;   // float4 index
    if (idx >= NTOK * H / 4) return;
    int elem = idx * 4;
    int n = elem / H;
    int h = elem % H;
    int r0 = g_slot_row[2 * n + 0];
    int r1 = g_slot_row[2 * n + 1];
    float4 a = *(const float4*)(g_y + (size_t)r0 * H + h);
    float4 b = *(const float4*)(g_y + (size_t)r1 * H + h);
    float4 o;
    o.x = a.x + b.x; o.y = a.y + b.y; o.z = a.z + b.z; o.w = a.w + b.w;
    *(float4*)(out + elem) = o;
}

// ---------------------------------------------------------------
extern "C" void kernel_launch(void* const* d_in, const int* in_sizes, int n_in,
                              void* d_out, int out_size) {
    const float* x  = (const float*)d_in[0];   // [1,1024,768]
    const float* rw = (const float*)d_in[1];   // [768,8]
    const float* w1 = (const float*)d_in[2];   // [8,768,3072]
    const float* w2 = (const float*)d_in[3];   // [8,3072,768]
    float* out = (float*)d_out;                // [1,1024,768]

    zero_cnt_kernel<<<1, 32>>>();
    router_kernel<<<NTOK / 8, 256>>>(x, rw);   // 8 warps/block, 1 warp/token

    dim3 g1(F / 128, NTOK / 128, E);           // (24, 8, 8)
    gemm1_kernel<<<g1, 256>>>(x, w1);

    dim3 g2(H / 128, NTOK / 128, E);           // (6, 8, 8)
    gemm2_kernel<<<g2, 256>>>(w2);

    combine_kernel<<<(NTOK * H / 4 + 255) / 256, 256>>>(out);
}

// round 3
// speedup vs baseline: 3.1180x; 3.1180x over previous
#include <cuda_runtime.h>
#include <math.h>
#include <stdint.h>

#define H    768
#define F    3072
#define E    8
#define NTOK 1024
#define CAP  1024
#define ROWS (E*CAP)

// ---- scratch (static device globals; no runtime allocation) ----
__device__ int   g_cnt[E];
__device__ int   g_tok[ROWS];
__device__ float g_rw[ROWS];
__device__ int   g_slot_row[NTOK*2];
__device__ float g_h[(size_t)ROWS * F];
__device__ float g_y[(size_t)ROWS * H];

// ---------------------------------------------------------------
__global__ void zero_cnt_kernel() {
    if (threadIdx.x < E) g_cnt[threadIdx.x] = 0;
}

__global__ void router_kernel(const float* __restrict__ x,
                              const float* __restrict__ rw) {
    int warp = (blockIdx.x * blockDim.x + threadIdx.x) >> 5;
    int lane = threadIdx.x & 31;
    if (warp >= NTOK) return;
    const float* xr = x + warp * H;

    float acc[E];
#pragma unroll
    for (int e = 0; e < E; e++) acc[e] = 0.f;
    for (int k = lane; k < H; k += 32) {
        float xv = xr[k];
        const float* r = rw + k * E;
#pragma unroll
        for (int e = 0; e < E; e++) acc[e] += xv * r[e];
    }
#pragma unroll
    for (int e = 0; e < E; e++) {
#pragma unroll
        for (int o = 16; o > 0; o >>= 1)
            acc[e] += __shfl_down_sync(0xffffffffu, acc[e], o);
    }
    if (lane == 0) {
        float b0 = -INFINITY, b1 = -INFINITY;
        int i0 = 0, i1 = 0;
#pragma unroll
        for (int e = 0; e < E; e++) {
            float v = acc[e];
            if (v > b0) { b1 = b0; i1 = i0; b0 = v; i0 = e; }
            else if (v > b1) { b1 = v; i1 = e; }
        }
        float s  = expf(b1 - b0);
        float w0 = 1.f / (1.f + s);
        float w1 = s / (1.f + s);

        int p0 = atomicAdd(&g_cnt[i0], 1);
        int r0 = i0 * CAP + p0;
        g_tok[r0] = warp; g_rw[r0] = w0; g_slot_row[warp * 2 + 0] = r0;

        int p1 = atomicAdd(&g_cnt[i1], 1);
        int r1 = i1 * CAP + p1;
        g_tok[r1] = warp; g_rw[r1] = w1; g_slot_row[warp * 2 + 1] = r1;
    }
}

__device__ __forceinline__ float gelu_exact(float v) {
    return 0.5f * v * (1.0f + erff(v * 0.70710678118654752f));
}

// ---------------------------------------------------------------
// tf32 MMA helpers
__device__ __forceinline__ uint32_t f2tf32(float f) {
    uint32_t u;
    asm("cvt.rna.tf32.f32 %0, %1;" : "=r"(u) : "f"(f));
    return u;
}
__device__ __forceinline__ void mma_tf32(float c[4],
                                         uint32_t a0, uint32_t a1, uint32_t a2, uint32_t a3,
                                         uint32_t b0, uint32_t b1) {
    asm volatile(
        "mma.sync.aligned.m16n8k8.row.col.f32.tf32.tf32.f32 "
        "{%0,%1,%2,%3},{%4,%5,%6,%7},{%8,%9},{%0,%1,%2,%3};"
        : "+f"(c[0]), "+f"(c[1]), "+f"(c[2]), "+f"(c[3])
        : "r"(a0), "r"(a1), "r"(a2), "r"(a3), "r"(b0), "r"(b1));
}

#define CP_ASYNC16(dst, src) \
    asm volatile("cp.async.cg.shared.global [%0], [%1], 16;" :: "r"(dst), "l"(src))
#define CP_COMMIT() asm volatile("cp.async.commit_group;")
#define CP_WAIT(n)  asm volatile("cp.async.wait_group %0;" :: "n"(n))

// ---------------------------------------------------------------
// Tensor-core FFN GEMM.  MODE 0: h = gelu(x_gathered @ w1)  (KD=768,  ND=3072)
//                        MODE 1: y = gate * (g_h @ w2)      (KD=3072, ND=768)
// A source is taken from g_h *inside device code* for MODE 1 (never pass a
// __device__ global as a host-side kernel arg).
// 128x128 tile, BK=16, 2-stage cp.async pipeline, 8 warps (2x4), warp = 64x32.
template<int KD, int ND, int MODE>
__global__ void __launch_bounds__(256, 2)
moe_mma_kernel(const float* __restrict__ Ax, const float* __restrict__ Bw) {
    const int e   = blockIdx.z;
    const int cnt = g_cnt[e];
    const int m0  = blockIdx.y * 128;
    if (m0 >= cnt) return;
    const int n0  = blockIdx.x * 128;

    __shared__ float As[2][128][20];   // [m][k]
    __shared__ float Bs[2][16][136];   // [k][n]

    const int t    = threadIdx.x;
    const int warp = t >> 5, lane = t & 31;
    const int wr = warp >> 2, wc = warp & 3;
    const int g  = lane >> 2, tg = lane & 3;

    // ---- global load mapping ----
    const int r0   = t >> 2;          // 0..63
    const int r1   = r0 + 64;
    const int segc = (t & 3) * 4;
    const float* aptr0;
    const float* aptr1;
    if (MODE == 0) {
        int ra = (m0 + r0 < cnt) ? g_tok[e * CAP + m0 + r0] : 0;
        int rb = (m0 + r1 < cnt) ? g_tok[e * CAP + m0 + r1] : 0;
        aptr0 = Ax + (size_t)ra * KD + segc;
        aptr1 = Ax + (size_t)rb * KD + segc;
    } else {
        int ra = e * CAP + ((m0 + r0 < cnt) ? m0 + r0 : 0);
        int rb = e * CAP + ((m0 + r1 < cnt) ? m0 + r1 : 0);
        aptr0 = g_h + (size_t)ra * KD + segc;   // device-side symbol reference
        aptr1 = g_h + (size_t)rb * KD + segc;
    }
    const int bk0  = t >> 5;
    const int bk1  = bk0 + 8;
    const int bseg = (t & 31) * 4;
    const float* bptr = Bw + (size_t)e * KD * ND + n0 + bseg;

    uint32_t dA0[2], dA1[2], dB0[2], dB1[2];
#pragma unroll
    for (int s = 0; s < 2; s++) {
        dA0[s] = (uint32_t)__cvta_generic_to_shared(&As[s][r0][segc]);
        dA1[s] = (uint32_t)__cvta_generic_to_shared(&As[s][r1][segc]);
        dB0[s] = (uint32_t)__cvta_generic_to_shared(&Bs[s][bk0][bseg]);
        dB1[s] = (uint32_t)__cvta_generic_to_shared(&Bs[s][bk1][bseg]);
    }

#define LOAD_STAGE(s, k0)                                              \
    do {                                                               \
        CP_ASYNC16(dA0[s], aptr0 + (k0));                              \
        CP_ASYNC16(dA1[s], aptr1 + (k0));                              \
        CP_ASYNC16(dB0[s], bptr + (size_t)((k0) + bk0) * ND);          \
        CP_ASYNC16(dB1[s], bptr + (size_t)((k0) + bk1) * ND);          \
    } while (0)

    float acc[4][4][4];
#pragma unroll
    for (int mt = 0; mt < 4; mt++)
#pragma unroll
        for (int nt = 0; nt < 4; nt++)
#pragma unroll
            for (int i = 0; i < 4; i++) acc[mt][nt][i] = 0.f;

    const int NIT = KD / 16;
    LOAD_STAGE(0, 0);
    CP_COMMIT();

    for (int it = 0; it < NIT; it++) {
        const int s = it & 1;
        if (it + 1 < NIT) {
            LOAD_STAGE(s ^ 1, (it + 1) * 16);
            CP_COMMIT();
            CP_WAIT(1);
        } else {
            CP_WAIT(0);
        }
        __syncthreads();

#pragma unroll
        for (int kk = 0; kk < 2; kk++) {
            const int kb = kk * 8;
            uint32_t af[4][4];
#pragma unroll
            for (int mt = 0; mt < 4; mt++) {
                int rr = wr * 64 + mt * 16 + g;
                af[mt][0] = f2tf32(As[s][rr][kb + tg]);
                af[mt][1] = f2tf32(As[s][rr + 8][kb + tg]);
                af[mt][2] = f2tf32(As[s][rr][kb + tg + 4]);
                af[mt][3] = f2tf32(As[s][rr + 8][kb + tg + 4]);
            }
            uint32_t bf[4][2];
#pragma unroll
            for (int nt = 0; nt < 4; nt++) {
                int cc = wc * 32 + nt * 8 + g;
                bf[nt][0] = f2tf32(Bs[s][kb + tg][cc]);
                bf[nt][1] = f2tf32(Bs[s][kb + tg + 4][cc]);
            }
#pragma unroll
            for (int mt = 0; mt < 4; mt++)
#pragma unroll
                for (int nt = 0; nt < 4; nt++)
                    mma_tf32(acc[mt][nt], af[mt][0], af[mt][1], af[mt][2], af[mt][3],
                             bf[nt][0], bf[nt][1]);
        }
        __syncthreads();
    }
#undef LOAD_STAGE

    // ---- epilogue ----
#pragma unroll
    for (int mt = 0; mt < 4; mt++) {
        int rloc0 = m0 + wr * 64 + mt * 16 + g;
        int rloc1 = rloc0 + 8;
#pragma unroll
        for (int nt = 0; nt < 4; nt++) {
            int cc = n0 + wc * 32 + nt * 8 + tg * 2;
            if (MODE == 0) {
                if (rloc0 < cnt) {
                    float* p = g_h + (size_t)(e * CAP + rloc0) * ND + cc;
                    p[0] = gelu_exact(acc[mt][nt][0]);
                    p[1] = gelu_exact(acc[mt][nt][1]);
                }
                if (rloc1 < cnt) {
                    float* p = g_h + (size_t)(e * CAP + rloc1) * ND + cc;
                    p[0] = gelu_exact(acc[mt][nt][2]);
                    p[1] = gelu_exact(acc[mt][nt][3]);
                }
            } else {
                if (rloc0 < cnt) {
                    int gr = e * CAP + rloc0;
                    float gate = g_rw[gr];
                    float* p = g_y + (size_t)gr * ND + cc;
                    p[0] = gate * acc[mt][nt][0];
                    p[1] = gate * acc[mt][nt][1];
                }
                if (rloc1 < cnt) {
                    int gr = e * CAP + rloc1;
                    float gate = g_rw[gr];
                    float* p = g_y + (size_t)gr * ND + cc;
                    p[0] = gate * acc[mt][nt][2];
                    p[1] = gate * acc[mt][nt][3];
                }
            }
        }
    }
}

// ---------------------------------------------------------------
__global__ void combine_kernel(float* __restrict__ out) {
    int idx = blockIdx.x * blockDim.x + threadIdx.x;
    if (idx >= NTOK * H / 4) return;
    int elem = idx * 4;
    int n = elem / H;
    int h = elem % H;
    int r0 = g_slot_row[2 * n + 0];
    int r1 = g_slot_row[2 * n + 1];
    float4 a = *(const float4*)(g_y + (size_t)r0 * H + h);
    float4 b = *(const float4*)(g_y + (size_t)r1 * H + h);
    float4 o;
    o.x = a.x + b.x; o.y = a.y + b.y; o.z = a.z + b.z; o.w = a.w + b.w;
    *(float4*)(out + elem) = o;
}

// ---------------------------------------------------------------
extern "C" void kernel_launch(void* const* d_in, const int* in_sizes, int n_in,
                              void* d_out, int out_size) {
    const float* x  = (const float*)d_in[0];
    const float* rw = (const float*)d_in[1];
    const float* w1 = (const float*)d_in[2];
    const float* w2 = (const float*)d_in[3];
    float* out = (float*)d_out;

    zero_cnt_kernel<<<1, 32>>>();
    router_kernel<<<NTOK / 8, 256>>>(x, rw);

    dim3 g1(F / 128, NTOK / 128, E);           // (24, 8, 8)
    moe_mma_kernel<H, F, 0><<<g1, 256>>>(x, w1);

    dim3 g2(H / 128, NTOK / 128, E);           // (6, 8, 8)
    moe_mma_kernel<F, H, 1><<<g2, 256>>>(nullptr, w2);  // A comes from g_h in-kernel

    combine_kernel<<<(NTOK * H / 4 + 255) / 256, 256>>>(out);
}

// round 4
// speedup vs baseline: 4.0687x; 1.3049x over previous
#include <cuda_runtime.h>
#include <math.h>
#include <stdint.h>

#define H    768
#define F    3072
#define E    8
#define NTOK 1024
#define CAP  1024
#define ROWS (E*CAP)
#define NSPLIT 3
#define KSPL (F / NSPLIT)   // 1024

// ---- scratch (static device globals; no runtime allocation) ----
__device__ int   g_cnt[E];
__device__ int   g_tok[ROWS];
__device__ float g_rw[ROWS];
__device__ int   g_slot_row[NTOK*2];
__device__ float g_h[(size_t)ROWS * F];
__device__ float g_ys[NSPLIT][(size_t)ROWS * H];

// ---------------------------------------------------------------
__global__ void zero_cnt_kernel() {
    if (threadIdx.x < E) g_cnt[threadIdx.x] = 0;
}

__global__ void router_kernel(const float* __restrict__ x,
                              const float* __restrict__ rw) {
    int warp = (blockIdx.x * blockDim.x + threadIdx.x) >> 5;
    int lane = threadIdx.x & 31;
    if (warp >= NTOK) return;
    const float* xr = x + warp * H;

    float acc[E];
#pragma unroll
    for (int e = 0; e < E; e++) acc[e] = 0.f;
    for (int k = lane; k < H; k += 32) {
        float xv = xr[k];
        const float* r = rw + k * E;
#pragma unroll
        for (int e = 0; e < E; e++) acc[e] += xv * r[e];
    }
#pragma unroll
    for (int e = 0; e < E; e++) {
#pragma unroll
        for (int o = 16; o > 0; o >>= 1)
            acc[e] += __shfl_down_sync(0xffffffffu, acc[e], o);
    }
    if (lane == 0) {
        float b0 = -INFINITY, b1 = -INFINITY;
        int i0 = 0, i1 = 0;
#pragma unroll
        for (int e = 0; e < E; e++) {
            float v = acc[e];
            if (v > b0) { b1 = b0; i1 = i0; b0 = v; i0 = e; }
            else if (v > b1) { b1 = v; i1 = e; }
        }
        float s  = expf(b1 - b0);
        float w0 = 1.f / (1.f + s);
        float w1 = s / (1.f + s);

        int p0 = atomicAdd(&g_cnt[i0], 1);
        int r0 = i0 * CAP + p0;
        g_tok[r0] = warp; g_rw[r0] = w0; g_slot_row[warp * 2 + 0] = r0;

        int p1 = atomicAdd(&g_cnt[i1], 1);
        int r1 = i1 * CAP + p1;
        g_tok[r1] = warp; g_rw[r1] = w1; g_slot_row[warp * 2 + 1] = r1;
    }
}

__device__ __forceinline__ float gelu_exact(float v) {
    return 0.5f * v * (1.0f + erff(v * 0.70710678118654752f));
}

// ---------------------------------------------------------------
__device__ __forceinline__ uint32_t f2tf32(float f) {
    uint32_t u;
    asm("cvt.rna.tf32.f32 %0, %1;" : "=r"(u) : "f"(f));
    return u;
}
__device__ __forceinline__ void mma_tf32(float c[4],
                                         uint32_t a0, uint32_t a1, uint32_t a2, uint32_t a3,
                                         uint32_t b0, uint32_t b1) {
    asm volatile(
        "mma.sync.aligned.m16n8k8.row.col.f32.tf32.tf32.f32 "
        "{%0,%1,%2,%3},{%4,%5,%6,%7},{%8,%9},{%0,%1,%2,%3};"
        : "+f"(c[0]), "+f"(c[1]), "+f"(c[2]), "+f"(c[3])
        : "r"(a0), "r"(a1), "r"(a2), "r"(a3), "r"(b0), "r"(b1));
}

#define CP_ASYNC16(dst, src) \
    asm volatile("cp.async.cg.shared.global [%0], [%1], 16;" :: "r"(dst), "l"(src))
#define CP_COMMIT() asm volatile("cp.async.commit_group;")
#define CP_WAIT(n)  asm volatile("cp.async.wait_group %0;" :: "n"(n))

// ---------------------------------------------------------------
// MODE 0: h = gelu(x_gathered @ w1)        KSTR=768,  KLEN=768,  ND=3072
//         grid.z = e
// MODE 1: ys[s] = g_h[rows, kbeg:kbeg+KLEN] @ w2[kbeg:,:]   (split-K partial)
//         KSTR=3072, KLEN=1024, ND=768, grid.z = e*NSPLIT + s
// 128x128 tile, BK=16, 2-stage cp.async, 8 warps (2x4), warp = 64x32.
template<int KSTR, int KLEN, int ND, int MODE>
__global__ void __launch_bounds__(256, 2)
moe_mma_kernel(const float* __restrict__ Ax, const float* __restrict__ Bw) {
    int e, spl;
    if (MODE == 0) { e = blockIdx.z; spl = 0; }
    else           { e = blockIdx.z / NSPLIT; spl = blockIdx.z % NSPLIT; }
    const int cnt = g_cnt[e];
    const int m0  = blockIdx.y * 128;
    if (m0 >= cnt) return;
    const int n0   = blockIdx.x * 128;
    const int kbeg = spl * KLEN;

    __shared__ float As[2][128][20];   // [m][k]
    __shared__ float Bs[2][16][136];   // [k][n]

    const int t    = threadIdx.x;
    const int warp = t >> 5, lane = t & 31;
    const int wr = warp >> 2, wc = warp & 3;
    const int g  = lane >> 2, tg = lane & 3;

    // ---- global load mapping ----
    const int r0   = t >> 2;          // 0..63
    const int r1   = r0 + 64;
    const int segc = (t & 3) * 4;
    const float* aptr0;
    const float* aptr1;
    if (MODE == 0) {
        int ra = (m0 + r0 < cnt) ? g_tok[e * CAP + m0 + r0] : 0;
        int rb = (m0 + r1 < cnt) ? g_tok[e * CAP + m0 + r1] : 0;
        aptr0 = Ax + (size_t)ra * KSTR + segc;
        aptr1 = Ax + (size_t)rb * KSTR + segc;
    } else {
        int ra = e * CAP + ((m0 + r0 < cnt) ? m0 + r0 : 0);
        int rb = e * CAP + ((m0 + r1 < cnt) ? m0 + r1 : 0);
        aptr0 = g_h + (size_t)ra * KSTR + kbeg + segc;
        aptr1 = g_h + (size_t)rb * KSTR + kbeg + segc;
    }
    const int bk0  = t >> 5;
    const int bk1  = bk0 + 8;
    const int bseg = (t & 31) * 4;
    const float* bptr = Bw + (size_t)e * KSTR * ND + (size_t)kbeg * ND + n0 + bseg;

    uint32_t dA0[2], dA1[2], dB0[2], dB1[2];
#pragma unroll
    for (int s = 0; s < 2; s++) {
        dA0[s] = (uint32_t)__cvta_generic_to_shared(&As[s][r0][segc]);
        dA1[s] = (uint32_t)__cvta_generic_to_shared(&As[s][r1][segc]);
        dB0[s] = (uint32_t)__cvta_generic_to_shared(&Bs[s][bk0][bseg]);
        dB1[s] = (uint32_t)__cvta_generic_to_shared(&Bs[s][bk1][bseg]);
    }

#define LOAD_STAGE(s, k0)                                              \
    do {                                                               \
        CP_ASYNC16(dA0[s], aptr0 + (k0));                              \
        CP_ASYNC16(dA1[s], aptr1 + (k0));                              \
        CP_ASYNC16(dB0[s], bptr + (size_t)((k0) + bk0) * ND);          \
        CP_ASYNC16(dB1[s], bptr + (size_t)((k0) + bk1) * ND);          \
    } while (0)

    float acc[4][4][4];
#pragma unroll
    for (int mt = 0; mt < 4; mt++)
#pragma unroll
        for (int nt = 0; nt < 4; nt++)
#pragma unroll
            for (int i = 0; i < 4; i++) acc[mt][nt][i] = 0.f;

    const int NIT = KLEN / 16;
    LOAD_STAGE(0, 0);
    CP_COMMIT();

    for (int it = 0; it < NIT; it++) {
        const int s = it & 1;
        if (it + 1 < NIT) {
            LOAD_STAGE(s ^ 1, (it + 1) * 16);
            CP_COMMIT();
            CP_WAIT(1);
        } else {
            CP_WAIT(0);
        }
        __syncthreads();

#pragma unroll
        for (int kk = 0; kk < 2; kk++) {
            const int kb = kk * 8;
            uint32_t af[4][4];
#pragma unroll
            for (int mt = 0; mt < 4; mt++) {
                int rr = wr * 64 + mt * 16 + g;
                af[mt][0] = f2tf32(As[s][rr][kb + tg]);
                af[mt][1] = f2tf32(As[s][rr + 8][kb + tg]);
                af[mt][2] = f2tf32(As[s][rr][kb + tg + 4]);
                af[mt][3] = f2tf32(As[s][rr + 8][kb + tg + 4]);
            }
            uint32_t bf[4][2];
#pragma unroll
            for (int nt = 0; nt < 4; nt++) {
                int cc = wc * 32 + nt * 8 + g;
                bf[nt][0] = f2tf32(Bs[s][kb + tg][cc]);
                bf[nt][1] = f2tf32(Bs[s][kb + tg + 4][cc]);
            }
#pragma unroll
            for (int mt = 0; mt < 4; mt++)
#pragma unroll
                for (int nt = 0; nt < 4; nt++)
                    mma_tf32(acc[mt][nt], af[mt][0], af[mt][1], af[mt][2], af[mt][3],
                             bf[nt][0], bf[nt][1]);
        }
        __syncthreads();
    }
#undef LOAD_STAGE

    // ---- epilogue ----
    float* ybase = (MODE == 0) ? g_h : (&g_ys[0][0] + (size_t)spl * ROWS * ND);
#pragma unroll
    for (int mt = 0; mt < 4; mt++) {
        int rloc0 = m0 + wr * 64 + mt * 16 + g;
        int rloc1 = rloc0 + 8;
#pragma unroll
        for (int nt = 0; nt < 4; nt++) {
            int cc = n0 + wc * 32 + nt * 8 + tg * 2;
            if (rloc0 < cnt) {
                float* p = ybase + (size_t)(e * CAP + rloc0) * ND + cc;
                if (MODE == 0) {
                    p[0] = gelu_exact(acc[mt][nt][0]);
                    p[1] = gelu_exact(acc[mt][nt][1]);
                } else {
                    p[0] = acc[mt][nt][0];
                    p[1] = acc[mt][nt][1];
                }
            }
            if (rloc1 < cnt) {
                float* p = ybase + (size_t)(e * CAP + rloc1) * ND + cc;
                if (MODE == 0) {
                    p[0] = gelu_exact(acc[mt][nt][2]);
                    p[1] = gelu_exact(acc[mt][nt][3]);
                } else {
                    p[0] = acc[mt][nt][2];
                    p[1] = acc[mt][nt][3];
                }
            }
        }
    }
}

// ---------------------------------------------------------------
// out[n, h] = gate0 * sum_s ys[s][r0, h] + gate1 * sum_s ys[s][r1, h]
__global__ void combine_kernel(float* __restrict__ out) {
    int idx = blockIdx.x * blockDim.x + threadIdx.x;
    if (idx >= NTOK * H / 4) return;
    int elem = idx * 4;
    int n = elem / H;
    int h = elem % H;
    int r0 = g_slot_row[2 * n + 0];
    int r1 = g_slot_row[2 * n + 1];
    float gw0 = g_rw[r0], gw1 = g_rw[r1];

    float4 s0 = make_float4(0.f, 0.f, 0.f, 0.f);
    float4 s1 = make_float4(0.f, 0.f, 0.f, 0.f);
#pragma unroll
    for (int s = 0; s < NSPLIT; s++) {
        float4 a = *(const float4*)(&g_ys[s][0] + (size_t)r0 * H + h);
        float4 b = *(const float4*)(&g_ys[s][0] + (size_t)r1 * H + h);
        s0.x += a.x; s0.y += a.y; s0.z += a.z; s0.w += a.w;
        s1.x += b.x; s1.y += b.y; s1.z += b.z; s1.w += b.w;
    }
    float4 o;
    o.x = gw0 * s0.x + gw1 * s1.x;
    o.y = gw0 * s0.y + gw1 * s1.y;
    o.z = gw0 * s0.z + gw1 * s1.z;
    o.w = gw0 * s0.w + gw1 * s1.w;
    *(float4*)(out + elem) = o;
}

// ---------------------------------------------------------------
extern "C" void kernel_launch(void* const* d_in, const int* in_sizes, int n_in,
                              void* d_out, int out_size) {
    const float* x  = (const float*)d_in[0];
    const float* rw = (const float*)d_in[1];
    const float* w1 = (const float*)d_in[2];
    const float* w2 = (const float*)d_in[3];
    float* out = (float*)d_out;

    zero_cnt_kernel<<<1, 32>>>();
    router_kernel<<<NTOK / 8, 256>>>(x, rw);

    dim3 g1(F / 128, NTOK / 128, E);                 // (24, 8, 8)
    moe_mma_kernel<H, H, F, 0><<<g1, 256>>>(x, w1);

    dim3 g2(H / 128, NTOK / 128, E * NSPLIT);        // (6, 8, 24)
    moe_mma_kernel<F, KSPL, H, 1><<<g2, 256>>>(nullptr, w2);

    combine_kernel<<<(NTOK * H / 4 + 255) / 256, 256>>>(out);
}